// round 15
// baseline (speedup 1.0000x reference)
#include <cuda_runtime.h>
#include <math.h>

#define NIMG 16
#define NCLS 80
#define NREF 256
#define CAP  8192
#define LCAP 8192
#define NSEG 6480       // segments per image (class-aligned 256-chunks)
#define NSEGPAD 6528
#define NW2  810        // minred warps per image (8 classes x 256 hw each)

#define MAGICF 12582912.0f              // 1.5 * 2^23 : round-to-nearest-int magic
#define KC (127 - 0x4B400000)           // exponent rebias for magic-rounded y
#define C1F 0.70710678f                 // quad minimax of 2^f on [-0.5, 0.5]
#define C2F 0.24264069f

typedef unsigned long long u64;

// ---------------- scratch (device globals; no allocs) ----------------
__device__ float g_segD[NIMG * NSEGPAD];            // per-segment min D
__device__ int   g_bcut[NIMG];
__device__ int   g_cnt[NIMG];
__device__ int   g_lcnt[NIMG];
__device__ int   g_seglist[NIMG][LCAP];
__device__ unsigned long long g_cand[NIMG][CAP];

struct P5 { const float* lg[5]; const float* rg[5]; const float* ct[5]; const float* lc[5]; };

__constant__ int c_HW[5]   = {15200, 3800, 950, 247, 70};
__constant__ int c_rb[5]   = {0, 1216000, 1520000, 1596000, 1615760};
__constant__ int c_spc[5]  = {60, 15, 4, 1, 1};
__constant__ int c_segb[5] = {0, 4800, 6000, 6320, 6400};
__constant__ float c_str[5] = {8.f, 16.f, 32.f, 64.f, 128.f};

// ---- packed f32x2 helpers (Blackwell PTX) ----
__device__ __forceinline__ u64 pk2(float lo, float hi) {
    u64 r; asm("mov.b64 %0,{%1,%2};" : "=l"(r) : "f"(lo), "f"(hi)); return r;
}
__device__ __forceinline__ void upk2(u64 v, float& lo, float& hi) {
    asm("mov.b64 {%0,%1},%2;" : "=f"(lo), "=f"(hi) : "l"(v));
}
__device__ __forceinline__ u64 mul2(u64 a, u64 b) {
    u64 r; asm("mul.rn.f32x2 %0,%1,%2;" : "=l"(r) : "l"(a), "l"(b)); return r;
}
__device__ __forceinline__ u64 add2(u64 a, u64 b) {
    u64 r; asm("add.rn.f32x2 %0,%1,%2;" : "=l"(r) : "l"(a), "l"(b)); return r;
}
__device__ __forceinline__ u64 fma2(u64 a, u64 b, u64 c) {
    u64 r; asm("fma.rn.f32x2 %0,%1,%2,%3;" : "=l"(r) : "l"(a), "l"(b), "l"(c)); return r;
}

// Scalar surrogate e^{-x}: magic-round exp2 split + quad minimax. Contraction-proof
// (__fmul_rn/__fadd_rn/fmaf): BITWISE identical to the packed expneg2 below.
__device__ __forceinline__ float expneg_s(float x) {
    float u = __fmul_rn(-1.44269504f, x);
    float y = __fadd_rn(u, MAGICF);
    int iy = __float_as_int(y);
    float yf = __fadd_rn(y, -MAGICF);
    float f = fmaf(yf, -1.0f, u);
    float pm = fmaf(fmaf(C2F, f, C1F), f, 1.0f);
    float sc = __int_as_float((iy + KC) << 23);
    return __fmul_rn(pm, sc);
}

// packed twin of expneg_s (per-lane IEEE rn ops -> identical bits)
__device__ __forceinline__ u64 expneg2(u64 x) {
    const u64 NL2  = pk2(-1.44269504f, -1.44269504f);
    const u64 MG   = pk2(MAGICF, MAGICF);
    const u64 NMG  = pk2(-MAGICF, -MAGICF);
    const u64 NONE = pk2(-1.0f, -1.0f);
    const u64 C2P  = pk2(C2F, C2F);
    const u64 C1P  = pk2(C1F, C1F);
    const u64 ONE  = pk2(1.0f, 1.0f);
    u64 u = mul2(x, NL2);
    u64 y = add2(u, MG);
    float ylo, yhi; upk2(y, ylo, yhi);
    u64 yf = add2(y, NMG);
    u64 f  = fma2(yf, NONE, u);
    u64 pm = fma2(fma2(C2P, f, C1P), f, ONE);
    float slo = __int_as_float((__float_as_int(ylo) + KC) << 23);
    float shi = __int_as_float((__float_as_int(yhi) + KC) << 23);
    return mul2(pm, pk2(slo, shi));
}

// surrogate inverse-score key from logit + precomputed denom cd = 1+e^-c
__device__ __forceinline__ float Dkey_s(float a, float cd) {
    return fmaf(expneg_s(a), cd, cd);             // (1 + e^-a) * cd
}

// Reference-exact sigmoid (libdevice expf == XLA f32 exp), survivors only.
__device__ __forceinline__ float sig_ref(float x) {
    return 1.0f / (1.0f + expf(-x));
}

struct Seg { int l, c, hw0, HW; };
__device__ __forceinline__ Seg seg_decode(int wid) {
    Seg s;
    if (wid < 4800)      { s.l=0; s.c=wid/60;  s.hw0=(wid-s.c*60)<<8;  s.HW=15200; }
    else if (wid < 6000) { int t=wid-4800; s.l=1; s.c=t/15; s.hw0=(t-s.c*15)<<8; s.HW=3800; }
    else if (wid < 6320) { int t=wid-6000; s.l=2; s.c=t>>2; s.hw0=(t&3)<<8; s.HW=950; }
    else if (wid < 6400) { s.l=3; s.c=wid-6320; s.hw0=0; s.HW=247; }
    else                 { s.l=4; s.c=wid-6400; s.hw0=0; s.HW=70; }
    return s;
}

// full pass: each warp handles 8 classes x 256 hw. ct loaded ONCE per window,
// surrogate denom computed inline. Packed f32x2 for levels 0/1; scalar
// (bitwise-identical) for levels 2-4.
__global__ void k_minred(P5 p) {
    int n = blockIdx.y;
    int w2 = blockIdx.x * 8 + (threadIdx.x >> 5);
    int lane = threadIdx.x & 31;
    if (w2 >= NW2) return;
    int l, grp, chunk;
    if (w2 < 600)      { l = 0; grp = w2 / 60;  chunk = w2 - grp * 60; }
    else if (w2 < 750) { int t = w2 - 600; l = 1; grp = t / 15; chunk = t - grp * 15; }
    else if (w2 < 790) { int t = w2 - 750; l = 2; grp = t >> 2; chunk = t & 3; }
    else if (w2 < 800) { l = 3; grp = w2 - 790; chunk = 0; }
    else               { l = 4; grp = w2 - 800; chunk = 0; }
    int HW = c_HW[l];
    int base = (chunk << 8) + lane * 8;
    const float* ctp = p.ct[l] + (size_t)n * HW;
    const float* lg0 = p.lg[l] + ((size_t)n * NCLS + grp * 8) * (size_t)HW;
    float mj[8];
    if (l < 2) {
        bool act = (base + 8 <= HW);
        u64 CD0, CD1, CD2, CD3;
        const u64 ONE = pk2(1.0f, 1.0f);
        if (act) {
            float4 t0 = *(const float4*)(ctp + base);
            float4 t1 = *(const float4*)(ctp + base + 4);
            CD0 = add2(expneg2(pk2(t0.x, t0.y)), ONE);
            CD1 = add2(expneg2(pk2(t0.z, t0.w)), ONE);
            CD2 = add2(expneg2(pk2(t1.x, t1.y)), ONE);
            CD3 = add2(expneg2(pk2(t1.z, t1.w)), ONE);
        }
        #pragma unroll
        for (int j = 0; j < 8; j++) {
            float m = 3.4e38f;
            if (act) {
                const float* lg = lg0 + (size_t)j * HW;
                float4 a0 = *(const float4*)(lg + base);
                float4 a1 = *(const float4*)(lg + base + 4);
                u64 D0 = fma2(expneg2(pk2(a0.x, a0.y)), CD0, CD0);
                u64 D1 = fma2(expneg2(pk2(a0.z, a0.w)), CD1, CD1);
                u64 D2 = fma2(expneg2(pk2(a1.x, a1.y)), CD2, CD2);
                u64 D3 = fma2(expneg2(pk2(a1.z, a1.w)), CD3, CD3);
                float x0, x1, x2, x3, x4, x5, x6, x7;
                upk2(D0, x0, x1); upk2(D1, x2, x3);
                upk2(D2, x4, x5); upk2(D3, x6, x7);
                m = fminf(fminf(fminf(x0, x1), fminf(x2, x3)),
                          fminf(fminf(x4, x5), fminf(x6, x7)));
            }
            mj[j] = m;
        }
    } else {
        float cdv[8];
        #pragma unroll
        for (int k = 0; k < 8; k++) {
            int h = base + k;
            cdv[k] = (h < HW) ? __fadd_rn(1.0f, expneg_s(ctp[h])) : 0.0f;
        }
        #pragma unroll
        for (int j = 0; j < 8; j++) {
            const float* lg = lg0 + (size_t)j * HW;
            float m = 3.4e38f;
            #pragma unroll
            for (int k = 0; k < 8; k++) {
                int h = base + k;
                if (h < HW) m = fminf(m, Dkey_s(lg[h], cdv[k]));
            }
            mj[j] = m;
        }
    }
    #pragma unroll
    for (int j = 0; j < 8; j++) {
        float m = mj[j];
        #pragma unroll
        for (int o = 16; o; o >>= 1)
            m = fminf(m, __shfl_xor_sync(0xffffffffu, m, o));
        mj[j] = m;
    }
    if (lane == 0) {
        int sb = c_segb[l], spc = c_spc[l];
        #pragma unroll
        for (int j = 0; j < 8; j++)
            g_segD[n * NSEGPAD + sb + (grp * 8 + j) * spc + chunk] = mj[j];
    }
}

// ascending rank-select over 4096 buckets of seg-mins, then build seglist.
__global__ void __launch_bounds__(512) k_cut() {
    __shared__ int hist[4096];
    __shared__ int wtot[16], wpre[16];
    __shared__ int bres, lcnt_s;
    int n = blockIdx.x, tid = threadIdx.x, nt = blockDim.x;
    int lane = tid & 31, w = tid >> 5;
    for (int i = tid; i < 4096; i += nt) hist[i] = 0;
    if (tid == 0) { bres = 4095; lcnt_s = 0; g_cnt[n] = 0; }
    __syncthreads();
    for (int i = tid; i < NSEG; i += nt) {
        unsigned b = __float_as_uint(g_segD[n * NSEGPAD + i]) >> 19;
        atomicAdd(&hist[min(b, 4095u)], 1);
    }
    __syncthreads();
    int s8 = 0;
    #pragma unroll
    for (int j = 0; j < 8; j++) s8 += hist[tid * 8 + j];
    int pre = s8;
    #pragma unroll
    for (int o = 1; o < 32; o <<= 1) {
        int t2 = __shfl_up_sync(0xffffffffu, pre, o);
        if (lane >= o) pre += t2;
    }
    if (lane == 31) wtot[w] = pre;
    __syncthreads();
    if (tid < 16) {
        int v = wtot[tid];
        int s = v;
        #pragma unroll
        for (int o = 1; o < 16; o <<= 1) {
            int t2 = __shfl_up_sync(0xffffu, s, o);
            if (tid >= o) s += t2;
        }
        wpre[tid] = s - v;
    }
    __syncthreads();
    int excl = wpre[w] + (pre - s8);
    if (excl < NREF && excl + s8 >= NREF) {
        int cum = excl;
        #pragma unroll
        for (int b = 0; b < 8; b++) {
            cum += hist[tid * 8 + b];
            if (cum >= NREF) { bres = tid * 8 + b; break; }
        }
    }
    __syncthreads();
    int bc = min(bres + 1, 4095);       // +1 bucket: surrogate-vs-exact slop
    if (tid == 0) g_bcut[n] = bc;
    for (int i = tid; i < NSEG; i += nt) {
        unsigned b = __float_as_uint(g_segD[n * NSEGPAD + i]) >> 19;
        if ((int)b <= bc) {
            int pos = atomicAdd(&lcnt_s, 1);
            if (pos < LCAP) g_seglist[n][pos] = i;
        }
    }
    __syncthreads();
    if (tid == 0) g_lcnt[n] = min(lcnt_s, LCAP);
}

__device__ __forceinline__ void push_cand(int n, float a, float ctr_v, int rnk) {
    float sa = sig_ref(a);
    if (sa > 0.05f) {                           // exact reference gate
        float v = sa * sig_ref(ctr_v);
        if (v > 0.0f) {
            unsigned long long kk =
                ((unsigned long long)__float_as_uint(v) << 32) |
                (0x7FFFFFFFu - (unsigned)rnk);
            int pos = atomicAdd(&g_cnt[n], 1);
            if (pos < CAP) g_cand[n][pos] = kk;
        }
    }
}

// flattened one-quad-per-thread, R11-proven grid (256,16).
__global__ void k_compact(P5 p) {
    int n = blockIdx.y;
    int bcut = g_bcut[n];
    int lcnt = g_lcnt[n];
    int total = lcnt << 6;              // 64 quads per 256-elem segment
    int stride = gridDim.x * blockDim.x;
    for (int e = blockIdx.x * blockDim.x + threadIdx.x; e < total; e += stride) {
        int si = g_seglist[n][e >> 6];
        Seg sg = seg_decode(si);
        int hw = sg.hw0 + ((e & 63) << 2);
        const float* lg = p.lg[sg.l] + ((size_t)n * NCLS + sg.c) * sg.HW;
        const float* ctp = p.ct[sg.l] + (size_t)n * sg.HW;
        int rb = c_rb[sg.l];
        if (sg.l < 2 && hw + 4 <= sg.HW) {
            float4 a = *(const float4*)(lg + hw);
            float4 t = *(const float4*)(ctp + hw);
            float aa[4] = {a.x, a.y, a.z, a.w};
            float tt[4] = {t.x, t.y, t.z, t.w};
            #pragma unroll
            for (int k = 0; k < 4; k++) {
                float cdv = __fadd_rn(1.0f, expneg_s(tt[k]));
                if ((int)(__float_as_uint(Dkey_s(aa[k], cdv)) >> 19) <= bcut)
                    push_cand(n, aa[k], tt[k], rb + (hw + k) * NCLS + sg.c);
            }
        } else {
            #pragma unroll
            for (int k = 0; k < 4; k++) {
                int h = hw + k;
                if (h < sg.HW) {
                    float a = lg[h];
                    float tv = ctp[h];
                    float cdv = __fadd_rn(1.0f, expneg_s(tv));
                    if ((int)(__float_as_uint(Dkey_s(a, cdv)) >> 19) <= bcut)
                        push_cand(n, a, tv, rb + h * NCLS + sg.c);
                }
            }
        }
    }
}

// top-256: 2048-bucket cut (scores < 1 -> bucket < 2032) -> balanced
// warp-per-survivor counting rank -> slots indirection -> parallel scatter.
__global__ void __launch_bounds__(1024) k_sort(P5 p, float* out) {
    __shared__ int hist[2048];           // 8KB; reused as slots[] after filter
    __shared__ u64 buf[2048];            // 16KB survivors
    __shared__ int wtot[32], wsuf[32];
    __shared__ int m, bs;
    int n = blockIdx.x, tid = threadIdx.x;
    const int nt = 1024;
    int lane = tid & 31, w = tid >> 5;
    int cnt = min(g_cnt[n], CAP);
    for (int i = tid; i < 2048; i += nt) hist[i] = 0;
    if (tid == 0) { m = 0; bs = 0; }
    __syncthreads();

    for (int i = tid; i < cnt; i += nt) {
        int b = (int)(g_cand[n][i] >> 51);     // < 2032 since 0 < score < 1
        atomicAdd(&hist[min(b, 2047)], 1);
    }
    __syncthreads();

    // descending rank-select over 2048 buckets; thread owns buckets {2t, 2t+1}
    {
        int c0 = hist[2 * tid], c1 = hist[2 * tid + 1];
        int s2 = c0 + c1;
        int suf = s2;
        #pragma unroll
        for (int o = 1; o < 32; o <<= 1) {
            int t2 = __shfl_down_sync(0xffffffffu, suf, o);
            if (lane + o < 32) suf += t2;
        }
        if (lane == 0) wtot[w] = suf;
        __syncthreads();
        if (tid < 32) {
            int v = wtot[tid];
            int s = v;
            #pragma unroll
            for (int o = 1; o < 32; o <<= 1) {
                int t2 = __shfl_down_sync(0xffffffffu, s, o);
                if (tid + o < 32) s += t2;
            }
            wsuf[tid] = s - v;
        }
        __syncthreads();
        int above = wsuf[w] + (suf - s2);
        if (above < NREF && above + s2 >= NREF) {
            int cum = above + c1;
            if (cum >= NREF) bs = 2 * tid + 1;
            else if (cum + c0 >= NREF) bs = 2 * tid;
        }
    }
    __syncthreads();
    int bcut2 = bs;
    __syncthreads();

    // filter survivors (bucket >= bs) into buf
    for (int i = tid; i < cnt; i += nt) {
        u64 kk = g_cand[n][i];
        if ((int)(kk >> 51) >= bcut2) {
            int pos = atomicAdd(&m, 1);
            if (pos < 2048) buf[pos] = kk;
        }
    }
    __syncthreads();
    int mm = min(m, 2048);
    int* slots = hist;                   // hist dead; reuse as slots

    // warp-per-survivor counting rank: lanes split the comparison range
    for (int si = w; si < mm; si += 32) {
        u64 key = buf[si];
        int c = 0;
        for (int j = lane; j < mm; j += 32)
            c += (buf[j] > key);
        #pragma unroll
        for (int o = 16; o; o >>= 1)
            c += __shfl_down_sync(0xffffffffu, c, o);
        if (lane == 0) slots[si] = c;
    }
    __syncthreads();

    // zero-fill output slots [mm, NREF)
    if (tid >= mm && tid < NREF) {
        int o = n * NREF + tid;
        out[o] = 0.f;
        float* ob = out + NIMG * NREF;
        ob[o * 4 + 0] = 0.f; ob[o * 4 + 1] = 0.f;
        ob[o * 4 + 2] = 0.f; ob[o * 4 + 3] = 0.f;
        out[NIMG * NREF * 5 + o] = 0.f;
        out[NIMG * NREF * 6 + o] = 0.f;
    }

    // parallel decode + scatter (one thread per survivor; independent loads)
    if (tid < mm) {
        int slot = slots[tid];
        if (slot < NREF) {
            u64 key = buf[tid];
            float v = __uint_as_float((unsigned)(key >> 32));
            unsigned rank = 0x7FFFFFFFu - (unsigned)(key & 0xFFFFFFFFu);
            int l;
            if (rank < 1216000u) l = 0;
            else if (rank < 1520000u) l = 1;
            else if (rank < 1596000u) l = 2;
            else if (rank < 1615760u) l = 3;
            else l = 4;
            int HWl = c_HW[l];
            int r = (int)rank - c_rb[l];
            int loc = r / NCLS;
            int cls = r - NCLS * loc;
            float strf = c_str[l];
            float px = p.lc[l][2 * loc], py = p.lc[l][2 * loc + 1];
            const float* rg = p.rg[l] + (size_t)n * 4 * HWl;
            float r0 = rg[loc] * strf;
            float r1 = rg[HWl + loc] * strf;
            float r2 = rg[2 * HWl + loc] * strf;
            float r3 = rg[3 * HWl + loc] * strf;
            int o = n * NREF + slot;
            out[o] = sqrtf(v);
            float* ob = out + NIMG * NREF;
            ob[o * 4 + 0] = px - r0; ob[o * 4 + 1] = py - r1;
            ob[o * 4 + 2] = px + r2; ob[o * 4 + 3] = py + r3;
            out[NIMG * NREF * 5 + o] = (float)cls;
            out[NIMG * NREF * 6 + o] = (float)l;
        }
    }
}

extern "C" void kernel_launch(void* const* d_in, const int* in_sizes, int n_in,
                              void* d_out, int out_size) {
    P5 p;
    for (int l = 0; l < 5; l++) {
        p.lg[l] = (const float*)d_in[4 * l + 0];
        p.rg[l] = (const float*)d_in[4 * l + 1];
        p.ct[l] = (const float*)d_in[4 * l + 2];
        p.lc[l] = (const float*)d_in[4 * l + 3];
    }
    dim3 g(102, NIMG);       // 102*8 = 816 warps >= 810 per image
    k_minred<<<g, 256>>>(p);
    k_cut<<<NIMG, 512>>>();
    dim3 gc(256, NIMG);      // R11-proven compact config (12.2us measured)
    k_compact<<<gc, 256>>>(p);
    k_sort<<<NIMG, 1024>>>(p, (float*)d_out);
}

// round 16
// speedup vs baseline: 1.0732x; 1.0732x over previous
#include <cuda_runtime.h>
#include <math.h>

#define NIMG 16
#define NCLS 80
#define NREF 256
#define CAP  8192
#define LCAP 8192
#define NSEG 6480       // segments per image (class-aligned 256-chunks)
#define NSEGPAD 6528
#define NW2  810        // minred warps per image (8 classes x 256 hw each)

#define MAGICF 12582912.0f              // 1.5 * 2^23 : round-to-nearest-int magic
#define KC (127 - 0x4B400000)           // exponent rebias for magic-rounded y
#define C1F 0.70710678f                 // quad minimax of 2^f on [-0.5, 0.5]
#define C2F 0.24264069f

typedef unsigned long long u64;

// ---------------- scratch (device globals; no allocs) ----------------
__device__ float g_segD[NIMG * NSEGPAD];            // per-segment min D
__device__ int   g_bcut[NIMG];
__device__ int   g_cnt[NIMG];
__device__ int   g_lcnt[NIMG];
__device__ int   g_seglist[NIMG][LCAP];
__device__ unsigned long long g_cand[NIMG][CAP];
__device__ int   g_hist2[NIMG][2048];               // exact-score buckets

struct P5 { const float* lg[5]; const float* rg[5]; const float* ct[5]; const float* lc[5]; };

__constant__ int c_HW[5]   = {15200, 3800, 950, 247, 70};
__constant__ int c_rb[5]   = {0, 1216000, 1520000, 1596000, 1615760};
__constant__ int c_spc[5]  = {60, 15, 4, 1, 1};
__constant__ int c_segb[5] = {0, 4800, 6000, 6320, 6400};
__constant__ float c_str[5] = {8.f, 16.f, 32.f, 64.f, 128.f};

// ---- packed f32x2 helpers (Blackwell PTX) ----
__device__ __forceinline__ u64 pk2(float lo, float hi) {
    u64 r; asm("mov.b64 %0,{%1,%2};" : "=l"(r) : "f"(lo), "f"(hi)); return r;
}
__device__ __forceinline__ void upk2(u64 v, float& lo, float& hi) {
    asm("mov.b64 {%0,%1},%2;" : "=f"(lo), "=f"(hi) : "l"(v));
}
__device__ __forceinline__ u64 mul2(u64 a, u64 b) {
    u64 r; asm("mul.rn.f32x2 %0,%1,%2;" : "=l"(r) : "l"(a), "l"(b)); return r;
}
__device__ __forceinline__ u64 add2(u64 a, u64 b) {
    u64 r; asm("add.rn.f32x2 %0,%1,%2;" : "=l"(r) : "l"(a), "l"(b)); return r;
}
__device__ __forceinline__ u64 fma2(u64 a, u64 b, u64 c) {
    u64 r; asm("fma.rn.f32x2 %0,%1,%2,%3;" : "=l"(r) : "l"(a), "l"(b), "l"(c)); return r;
}

// Scalar surrogate e^{-x}: magic-round exp2 split + quad minimax. Contraction-proof
// (__fmul_rn/__fadd_rn/fmaf): BITWISE identical to the packed expneg2 below.
__device__ __forceinline__ float expneg_s(float x) {
    float u = __fmul_rn(-1.44269504f, x);
    float y = __fadd_rn(u, MAGICF);
    int iy = __float_as_int(y);
    float yf = __fadd_rn(y, -MAGICF);
    float f = fmaf(yf, -1.0f, u);
    float pm = fmaf(fmaf(C2F, f, C1F), f, 1.0f);
    float sc = __int_as_float((iy + KC) << 23);
    return __fmul_rn(pm, sc);
}

// packed twin of expneg_s (per-lane IEEE rn ops -> identical bits)
__device__ __forceinline__ u64 expneg2(u64 x) {
    const u64 NL2  = pk2(-1.44269504f, -1.44269504f);
    const u64 MG   = pk2(MAGICF, MAGICF);
    const u64 NMG  = pk2(-MAGICF, -MAGICF);
    const u64 NONE = pk2(-1.0f, -1.0f);
    const u64 C2P  = pk2(C2F, C2F);
    const u64 C1P  = pk2(C1F, C1F);
    const u64 ONE  = pk2(1.0f, 1.0f);
    u64 u = mul2(x, NL2);
    u64 y = add2(u, MG);
    float ylo, yhi; upk2(y, ylo, yhi);
    u64 yf = add2(y, NMG);
    u64 f  = fma2(yf, NONE, u);
    u64 pm = fma2(fma2(C2P, f, C1P), f, ONE);
    float slo = __int_as_float((__float_as_int(ylo) + KC) << 23);
    float shi = __int_as_float((__float_as_int(yhi) + KC) << 23);
    return mul2(pm, pk2(slo, shi));
}

// surrogate inverse-score key from logit + precomputed denom cd = 1+e^-c
__device__ __forceinline__ float Dkey_s(float a, float cd) {
    return fmaf(expneg_s(a), cd, cd);             // (1 + e^-a) * cd
}

// Reference-exact sigmoid (libdevice expf == XLA f32 exp), survivors only.
__device__ __forceinline__ float sig_ref(float x) {
    return 1.0f / (1.0f + expf(-x));
}

struct Seg { int l, c, hw0, HW; };
__device__ __forceinline__ Seg seg_decode(int wid) {
    Seg s;
    if (wid < 4800)      { s.l=0; s.c=wid/60;  s.hw0=(wid-s.c*60)<<8;  s.HW=15200; }
    else if (wid < 6000) { int t=wid-4800; s.l=1; s.c=t/15; s.hw0=(t-s.c*15)<<8; s.HW=3800; }
    else if (wid < 6320) { int t=wid-6000; s.l=2; s.c=t>>2; s.hw0=(t&3)<<8; s.HW=950; }
    else if (wid < 6400) { s.l=3; s.c=wid-6320; s.hw0=0; s.HW=247; }
    else                 { s.l=4; s.c=wid-6400; s.hw0=0; s.HW=70; }
    return s;
}

// full pass: each warp handles 8 classes x 256 hw. ct loaded ONCE per window,
// surrogate denom computed inline. Packed f32x2 for levels 0/1; scalar
// (bitwise-identical) for levels 2-4.
__global__ void k_minred(P5 p) {
    int n = blockIdx.y;
    int w2 = blockIdx.x * 8 + (threadIdx.x >> 5);
    int lane = threadIdx.x & 31;
    if (w2 >= NW2) return;
    int l, grp, chunk;
    if (w2 < 600)      { l = 0; grp = w2 / 60;  chunk = w2 - grp * 60; }
    else if (w2 < 750) { int t = w2 - 600; l = 1; grp = t / 15; chunk = t - grp * 15; }
    else if (w2 < 790) { int t = w2 - 750; l = 2; grp = t >> 2; chunk = t & 3; }
    else if (w2 < 800) { l = 3; grp = w2 - 790; chunk = 0; }
    else               { l = 4; grp = w2 - 800; chunk = 0; }
    int HW = c_HW[l];
    int base = (chunk << 8) + lane * 8;
    const float* ctp = p.ct[l] + (size_t)n * HW;
    const float* lg0 = p.lg[l] + ((size_t)n * NCLS + grp * 8) * (size_t)HW;
    float mj[8];
    if (l < 2) {
        bool act = (base + 8 <= HW);
        u64 CD0, CD1, CD2, CD3;
        const u64 ONE = pk2(1.0f, 1.0f);
        if (act) {
            float4 t0 = *(const float4*)(ctp + base);
            float4 t1 = *(const float4*)(ctp + base + 4);
            CD0 = add2(expneg2(pk2(t0.x, t0.y)), ONE);
            CD1 = add2(expneg2(pk2(t0.z, t0.w)), ONE);
            CD2 = add2(expneg2(pk2(t1.x, t1.y)), ONE);
            CD3 = add2(expneg2(pk2(t1.z, t1.w)), ONE);
        }
        #pragma unroll
        for (int j = 0; j < 8; j++) {
            float m = 3.4e38f;
            if (act) {
                const float* lg = lg0 + (size_t)j * HW;
                float4 a0 = *(const float4*)(lg + base);
                float4 a1 = *(const float4*)(lg + base + 4);
                u64 D0 = fma2(expneg2(pk2(a0.x, a0.y)), CD0, CD0);
                u64 D1 = fma2(expneg2(pk2(a0.z, a0.w)), CD1, CD1);
                u64 D2 = fma2(expneg2(pk2(a1.x, a1.y)), CD2, CD2);
                u64 D3 = fma2(expneg2(pk2(a1.z, a1.w)), CD3, CD3);
                float x0, x1, x2, x3, x4, x5, x6, x7;
                upk2(D0, x0, x1); upk2(D1, x2, x3);
                upk2(D2, x4, x5); upk2(D3, x6, x7);
                m = fminf(fminf(fminf(x0, x1), fminf(x2, x3)),
                          fminf(fminf(x4, x5), fminf(x6, x7)));
            }
            mj[j] = m;
        }
    } else {
        float cdv[8];
        #pragma unroll
        for (int k = 0; k < 8; k++) {
            int h = base + k;
            cdv[k] = (h < HW) ? __fadd_rn(1.0f, expneg_s(ctp[h])) : 0.0f;
        }
        #pragma unroll
        for (int j = 0; j < 8; j++) {
            const float* lg = lg0 + (size_t)j * HW;
            float m = 3.4e38f;
            #pragma unroll
            for (int k = 0; k < 8; k++) {
                int h = base + k;
                if (h < HW) m = fminf(m, Dkey_s(lg[h], cdv[k]));
            }
            mj[j] = m;
        }
    }
    #pragma unroll
    for (int j = 0; j < 8; j++) {
        float m = mj[j];
        #pragma unroll
        for (int o = 16; o; o >>= 1)
            m = fminf(m, __shfl_xor_sync(0xffffffffu, m, o));
        mj[j] = m;
    }
    if (lane == 0) {
        int sb = c_segb[l], spc = c_spc[l];
        #pragma unroll
        for (int j = 0; j < 8; j++)
            g_segD[n * NSEGPAD + sb + (grp * 8 + j) * spc + chunk] = mj[j];
    }
}

// ascending rank-select over 4096 buckets of seg-mins, then build seglist.
// Also zeroes g_cnt and g_hist2.
__global__ void __launch_bounds__(512) k_cut() {
    __shared__ int hist[4096];
    __shared__ int wtot[16], wpre[16];
    __shared__ int bres, lcnt_s;
    int n = blockIdx.x, tid = threadIdx.x, nt = blockDim.x;
    int lane = tid & 31, w = tid >> 5;
    for (int i = tid; i < 4096; i += nt) hist[i] = 0;
    for (int i = tid; i < 2048; i += nt) g_hist2[n][i] = 0;
    if (tid == 0) { bres = 4095; lcnt_s = 0; g_cnt[n] = 0; }
    __syncthreads();
    for (int i = tid; i < NSEG; i += nt) {
        unsigned b = __float_as_uint(g_segD[n * NSEGPAD + i]) >> 19;
        atomicAdd(&hist[min(b, 4095u)], 1);
    }
    __syncthreads();
    int s8 = 0;
    #pragma unroll
    for (int j = 0; j < 8; j++) s8 += hist[tid * 8 + j];
    int pre = s8;
    #pragma unroll
    for (int o = 1; o < 32; o <<= 1) {
        int t2 = __shfl_up_sync(0xffffffffu, pre, o);
        if (lane >= o) pre += t2;
    }
    if (lane == 31) wtot[w] = pre;
    __syncthreads();
    if (tid < 16) {
        int v = wtot[tid];
        int s = v;
        #pragma unroll
        for (int o = 1; o < 16; o <<= 1) {
            int t2 = __shfl_up_sync(0xffffu, s, o);
            if (tid >= o) s += t2;
        }
        wpre[tid] = s - v;
    }
    __syncthreads();
    int excl = wpre[w] + (pre - s8);
    if (excl < NREF && excl + s8 >= NREF) {
        int cum = excl;
        #pragma unroll
        for (int b = 0; b < 8; b++) {
            cum += hist[tid * 8 + b];
            if (cum >= NREF) { bres = tid * 8 + b; break; }
        }
    }
    __syncthreads();
    int bc = min(bres + 1, 4095);       // +1 bucket: surrogate-vs-exact slop
    if (tid == 0) g_bcut[n] = bc;
    for (int i = tid; i < NSEG; i += nt) {
        unsigned b = __float_as_uint(g_segD[n * NSEGPAD + i]) >> 19;
        if ((int)b <= bc) {
            int pos = atomicAdd(&lcnt_s, 1);
            if (pos < LCAP) g_seglist[n][pos] = i;
        }
    }
    __syncthreads();
    if (tid == 0) g_lcnt[n] = min(lcnt_s, LCAP);
}

// emit candidate AND bump the per-image exact-score histogram (stored-only,
// so k_sort's scan sees the identical multiset as the filter).
__device__ __forceinline__ void push_cand(int n, float a, float ctr_v, int rnk) {
    float sa = sig_ref(a);
    if (sa > 0.05f) {                           // exact reference gate
        float v = sa * sig_ref(ctr_v);
        if (v > 0.0f) {
            unsigned vb = __float_as_uint(v);
            unsigned long long kk =
                ((unsigned long long)vb << 32) |
                (0x7FFFFFFFu - (unsigned)rnk);
            int pos = atomicAdd(&g_cnt[n], 1);
            if (pos < CAP) {
                g_cand[n][pos] = kk;
                atomicAdd(&g_hist2[n][min(vb >> 19, 2047u)], 1);
            }
        }
    }
}

// flattened one-quad-per-thread, R11-proven grid (256,16).
__global__ void k_compact(P5 p) {
    int n = blockIdx.y;
    int bcut = g_bcut[n];
    int lcnt = g_lcnt[n];
    int total = lcnt << 6;              // 64 quads per 256-elem segment
    int stride = gridDim.x * blockDim.x;
    for (int e = blockIdx.x * blockDim.x + threadIdx.x; e < total; e += stride) {
        int si = g_seglist[n][e >> 6];
        Seg sg = seg_decode(si);
        int hw = sg.hw0 + ((e & 63) << 2);
        const float* lg = p.lg[sg.l] + ((size_t)n * NCLS + sg.c) * sg.HW;
        const float* ctp = p.ct[sg.l] + (size_t)n * sg.HW;
        int rb = c_rb[sg.l];
        if (sg.l < 2 && hw + 4 <= sg.HW) {
            float4 a = *(const float4*)(lg + hw);
            float4 t = *(const float4*)(ctp + hw);
            float aa[4] = {a.x, a.y, a.z, a.w};
            float tt[4] = {t.x, t.y, t.z, t.w};
            #pragma unroll
            for (int k = 0; k < 4; k++) {
                float cdv = __fadd_rn(1.0f, expneg_s(tt[k]));
                if ((int)(__float_as_uint(Dkey_s(aa[k], cdv)) >> 19) <= bcut)
                    push_cand(n, aa[k], tt[k], rb + (hw + k) * NCLS + sg.c);
            }
        } else {
            #pragma unroll
            for (int k = 0; k < 4; k++) {
                int h = hw + k;
                if (h < sg.HW) {
                    float a = lg[h];
                    float tv = ctp[h];
                    float cdv = __fadd_rn(1.0f, expneg_s(tv));
                    if ((int)(__float_as_uint(Dkey_s(a, cdv)) >> 19) <= bcut)
                        push_cand(n, a, tv, rb + h * NCLS + sg.c);
                }
            }
        }
    }
}

// top-256: scan precomputed 2048-bucket hist -> filter -> serial broadcast
// counting rank (R14-proven) with inline scatter.
__global__ void __launch_bounds__(1024) k_sort(P5 p, float* out) {
    __shared__ u64 buf[2048];            // 16KB survivors
    __shared__ int wtot[32], wsuf[32];
    __shared__ int m, bs;
    int n = blockIdx.x, tid = threadIdx.x;
    const int nt = 1024;
    int lane = tid & 31, w = tid >> 5;
    int cnt = min(g_cnt[n], CAP);
    if (tid == 0) { m = 0; bs = 0; }
    __syncthreads();

    // descending rank-select over precomputed 2048 buckets (thread owns 2t,2t+1)
    {
        int c0 = g_hist2[n][2 * tid], c1 = g_hist2[n][2 * tid + 1];
        int s2 = c0 + c1;
        int suf = s2;
        #pragma unroll
        for (int o = 1; o < 32; o <<= 1) {
            int t2 = __shfl_down_sync(0xffffffffu, suf, o);
            if (lane + o < 32) suf += t2;
        }
        if (lane == 0) wtot[w] = suf;
        __syncthreads();
        if (tid < 32) {
            int v = wtot[tid];
            int s = v;
            #pragma unroll
            for (int o = 1; o < 32; o <<= 1) {
                int t2 = __shfl_down_sync(0xffffffffu, s, o);
                if (tid + o < 32) s += t2;
            }
            wsuf[tid] = s - v;
        }
        __syncthreads();
        int above = wsuf[w] + (suf - s2);
        if (above < NREF && above + s2 >= NREF) {
            int cum = above + c1;
            if (cum >= NREF) bs = 2 * tid + 1;
            else if (cum + c0 >= NREF) bs = 2 * tid;
        }
    }
    __syncthreads();
    int bcut2 = bs;

    // filter survivors (bucket >= bs) into buf
    for (int i = tid; i < cnt; i += nt) {
        u64 kk = g_cand[n][i];
        if ((int)(kk >> 51) >= bcut2) {
            int pos = atomicAdd(&m, 1);
            if (pos < 2048) buf[pos] = kk;
        }
    }
    __syncthreads();
    int mm = min(m, 2048);

    // zero-fill output slots [mm, NREF) (disjoint from scatter targets < mm)
    if (tid >= mm && tid < NREF) {
        int o = n * NREF + tid;
        out[o] = 0.f;
        float* ob = out + NIMG * NREF;
        ob[o * 4 + 0] = 0.f; ob[o * 4 + 1] = 0.f;
        ob[o * 4 + 2] = 0.f; ob[o * 4 + 3] = 0.f;
        out[NIMG * NREF * 5 + o] = 0.f;
        out[NIMG * NREF * 6 + o] = 0.f;
    }

    // counting rank (broadcast smem reads) + inline scatter
    for (int i = tid; i < mm; i += nt) {
        u64 key = buf[i];
        int slot = 0;
        for (int j = 0; j < mm; j++)
            slot += (buf[j] > key);
        if (slot < NREF) {
            float v = __uint_as_float((unsigned)(key >> 32));
            unsigned rank = 0x7FFFFFFFu - (unsigned)(key & 0xFFFFFFFFu);
            int l;
            if (rank < 1216000u) l = 0;
            else if (rank < 1520000u) l = 1;
            else if (rank < 1596000u) l = 2;
            else if (rank < 1615760u) l = 3;
            else l = 4;
            int HWl = c_HW[l];
            int r = (int)rank - c_rb[l];
            int loc = r / NCLS;
            int cls = r - NCLS * loc;
            float strf = c_str[l];
            float px = p.lc[l][2 * loc], py = p.lc[l][2 * loc + 1];
            const float* rg = p.rg[l] + (size_t)n * 4 * HWl;
            float r0 = rg[loc] * strf;
            float r1 = rg[HWl + loc] * strf;
            float r2 = rg[2 * HWl + loc] * strf;
            float r3 = rg[3 * HWl + loc] * strf;
            int o = n * NREF + slot;
            out[o] = sqrtf(v);
            float* ob = out + NIMG * NREF;
            ob[o * 4 + 0] = px - r0; ob[o * 4 + 1] = py - r1;
            ob[o * 4 + 2] = px + r2; ob[o * 4 + 3] = py + r3;
            out[NIMG * NREF * 5 + o] = (float)cls;
            out[NIMG * NREF * 6 + o] = (float)l;
        }
    }
}

extern "C" void kernel_launch(void* const* d_in, const int* in_sizes, int n_in,
                              void* d_out, int out_size) {
    P5 p;
    for (int l = 0; l < 5; l++) {
        p.lg[l] = (const float*)d_in[4 * l + 0];
        p.rg[l] = (const float*)d_in[4 * l + 1];
        p.ct[l] = (const float*)d_in[4 * l + 2];
        p.lc[l] = (const float*)d_in[4 * l + 3];
    }
    dim3 g(102, NIMG);       // 102*8 = 816 warps >= 810 per image
    k_minred<<<g, 256>>>(p);
    k_cut<<<NIMG, 512>>>();
    dim3 gc(256, NIMG);      // R11-proven compact config
    k_compact<<<gc, 256>>>(p);
    k_sort<<<NIMG, 1024>>>(p, (float*)d_out);
}

// round 17
// speedup vs baseline: 1.1286x; 1.0516x over previous
#include <cuda_runtime.h>
#include <math.h>

#define NIMG 16
#define NCLS 80
#define NREF 256
#define CAP  8192
#define LCAP 8192
#define NSEG 6480       // segments per image (class-aligned 256-chunks)
#define NSEGPAD 6528
#define NW2  810        // minred warps per image (8 classes x 256 hw each)
#define BOFF 2032       // D > 1 strictly -> segD bucket >= 2032

#define MAGICF 12582912.0f              // 1.5 * 2^23 : round-to-nearest-int magic
#define KC (127 - 0x4B400000)           // exponent rebias for magic-rounded y
#define C1F 0.70710678f                 // quad minimax of 2^f on [-0.5, 0.5]
#define C2F 0.24264069f

typedef unsigned long long u64;

// ---------------- scratch (device globals; no allocs) ----------------
__device__ float g_segD[NIMG * NSEGPAD];            // per-segment min D
__device__ int   g_bcut[NIMG];
__device__ int   g_cnt[NIMG];
__device__ int   g_lcnt[NIMG];
__device__ int   g_seglist[NIMG][LCAP];
__device__ unsigned long long g_cand[NIMG][CAP];
__device__ int   g_hist2[NIMG][2048];               // exact-score buckets

struct P5 { const float* lg[5]; const float* rg[5]; const float* ct[5]; const float* lc[5]; };

__constant__ int c_HW[5]   = {15200, 3800, 950, 247, 70};
__constant__ int c_rb[5]   = {0, 1216000, 1520000, 1596000, 1615760};
__constant__ int c_spc[5]  = {60, 15, 4, 1, 1};
__constant__ int c_segb[5] = {0, 4800, 6000, 6320, 6400};
__constant__ float c_str[5] = {8.f, 16.f, 32.f, 64.f, 128.f};

// ---- packed f32x2 helpers (Blackwell PTX) ----
__device__ __forceinline__ u64 pk2(float lo, float hi) {
    u64 r; asm("mov.b64 %0,{%1,%2};" : "=l"(r) : "f"(lo), "f"(hi)); return r;
}
__device__ __forceinline__ void upk2(u64 v, float& lo, float& hi) {
    asm("mov.b64 {%0,%1},%2;" : "=f"(lo), "=f"(hi) : "l"(v));
}
__device__ __forceinline__ u64 mul2(u64 a, u64 b) {
    u64 r; asm("mul.rn.f32x2 %0,%1,%2;" : "=l"(r) : "l"(a), "l"(b)); return r;
}
__device__ __forceinline__ u64 add2(u64 a, u64 b) {
    u64 r; asm("add.rn.f32x2 %0,%1,%2;" : "=l"(r) : "l"(a), "l"(b)); return r;
}
__device__ __forceinline__ u64 fma2(u64 a, u64 b, u64 c) {
    u64 r; asm("fma.rn.f32x2 %0,%1,%2,%3;" : "=l"(r) : "l"(a), "l"(b), "l"(c)); return r;
}

// Scalar surrogate e^{-x}: magic-round exp2 split + quad minimax. Contraction-proof
// (__fmul_rn/__fadd_rn/fmaf): BITWISE identical to the packed expneg2 below.
__device__ __forceinline__ float expneg_s(float x) {
    float u = __fmul_rn(-1.44269504f, x);
    float y = __fadd_rn(u, MAGICF);
    int iy = __float_as_int(y);
    float yf = __fadd_rn(y, -MAGICF);
    float f = fmaf(yf, -1.0f, u);
    float pm = fmaf(fmaf(C2F, f, C1F), f, 1.0f);
    float sc = __int_as_float((iy + KC) << 23);
    return __fmul_rn(pm, sc);
}

// packed twin of expneg_s (per-lane IEEE rn ops -> identical bits)
__device__ __forceinline__ u64 expneg2(u64 x) {
    const u64 NL2  = pk2(-1.44269504f, -1.44269504f);
    const u64 MG   = pk2(MAGICF, MAGICF);
    const u64 NMG  = pk2(-MAGICF, -MAGICF);
    const u64 NONE = pk2(-1.0f, -1.0f);
    const u64 C2P  = pk2(C2F, C2F);
    const u64 C1P  = pk2(C1F, C1F);
    const u64 ONE  = pk2(1.0f, 1.0f);
    u64 u = mul2(x, NL2);
    u64 y = add2(u, MG);
    float ylo, yhi; upk2(y, ylo, yhi);
    u64 yf = add2(y, NMG);
    u64 f  = fma2(yf, NONE, u);
    u64 pm = fma2(fma2(C2P, f, C1P), f, ONE);
    float slo = __int_as_float((__float_as_int(ylo) + KC) << 23);
    float shi = __int_as_float((__float_as_int(yhi) + KC) << 23);
    return mul2(pm, pk2(slo, shi));
}

// surrogate inverse-score key from logit + precomputed denom cd = 1+e^-c
__device__ __forceinline__ float Dkey_s(float a, float cd) {
    return fmaf(expneg_s(a), cd, cd);             // (1 + e^-a) * cd
}

// Reference-exact sigmoid (libdevice expf == XLA f32 exp), survivors only.
__device__ __forceinline__ float sig_ref(float x) {
    return 1.0f / (1.0f + expf(-x));
}

struct Seg { int l, c, hw0, HW; };
__device__ __forceinline__ Seg seg_decode(int wid) {
    Seg s;
    if (wid < 4800)      { s.l=0; s.c=wid/60;  s.hw0=(wid-s.c*60)<<8;  s.HW=15200; }
    else if (wid < 6000) { int t=wid-4800; s.l=1; s.c=t/15; s.hw0=(t-s.c*15)<<8; s.HW=3800; }
    else if (wid < 6320) { int t=wid-6000; s.l=2; s.c=t>>2; s.hw0=(t&3)<<8; s.HW=950; }
    else if (wid < 6400) { s.l=3; s.c=wid-6320; s.hw0=0; s.HW=247; }
    else                 { s.l=4; s.c=wid-6400; s.hw0=0; s.HW=70; }
    return s;
}

// full pass: each warp handles 8 classes x 256 hw. ct loaded ONCE per window,
// surrogate denom computed inline. Packed f32x2 for levels 0/1; scalar
// (bitwise-identical) for levels 2-4.
__global__ void k_minred(P5 p) {
    int n = blockIdx.y;
    int w2 = blockIdx.x * 8 + (threadIdx.x >> 5);
    int lane = threadIdx.x & 31;
    if (w2 >= NW2) return;
    int l, grp, chunk;
    if (w2 < 600)      { l = 0; grp = w2 / 60;  chunk = w2 - grp * 60; }
    else if (w2 < 750) { int t = w2 - 600; l = 1; grp = t / 15; chunk = t - grp * 15; }
    else if (w2 < 790) { int t = w2 - 750; l = 2; grp = t >> 2; chunk = t & 3; }
    else if (w2 < 800) { l = 3; grp = w2 - 790; chunk = 0; }
    else               { l = 4; grp = w2 - 800; chunk = 0; }
    int HW = c_HW[l];
    int base = (chunk << 8) + lane * 8;
    const float* ctp = p.ct[l] + (size_t)n * HW;
    const float* lg0 = p.lg[l] + ((size_t)n * NCLS + grp * 8) * (size_t)HW;
    float mj[8];
    if (l < 2) {
        bool act = (base + 8 <= HW);
        u64 CD0, CD1, CD2, CD3;
        const u64 ONE = pk2(1.0f, 1.0f);
        if (act) {
            float4 t0 = *(const float4*)(ctp + base);
            float4 t1 = *(const float4*)(ctp + base + 4);
            CD0 = add2(expneg2(pk2(t0.x, t0.y)), ONE);
            CD1 = add2(expneg2(pk2(t0.z, t0.w)), ONE);
            CD2 = add2(expneg2(pk2(t1.x, t1.y)), ONE);
            CD3 = add2(expneg2(pk2(t1.z, t1.w)), ONE);
        }
        #pragma unroll
        for (int j = 0; j < 8; j++) {
            float m = 3.4e38f;
            if (act) {
                const float* lg = lg0 + (size_t)j * HW;
                float4 a0 = *(const float4*)(lg + base);
                float4 a1 = *(const float4*)(lg + base + 4);
                u64 D0 = fma2(expneg2(pk2(a0.x, a0.y)), CD0, CD0);
                u64 D1 = fma2(expneg2(pk2(a0.z, a0.w)), CD1, CD1);
                u64 D2 = fma2(expneg2(pk2(a1.x, a1.y)), CD2, CD2);
                u64 D3 = fma2(expneg2(pk2(a1.z, a1.w)), CD3, CD3);
                float x0, x1, x2, x3, x4, x5, x6, x7;
                upk2(D0, x0, x1); upk2(D1, x2, x3);
                upk2(D2, x4, x5); upk2(D3, x6, x7);
                m = fminf(fminf(fminf(x0, x1), fminf(x2, x3)),
                          fminf(fminf(x4, x5), fminf(x6, x7)));
            }
            mj[j] = m;
        }
    } else {
        float cdv[8];
        #pragma unroll
        for (int k = 0; k < 8; k++) {
            int h = base + k;
            cdv[k] = (h < HW) ? __fadd_rn(1.0f, expneg_s(ctp[h])) : 0.0f;
        }
        #pragma unroll
        for (int j = 0; j < 8; j++) {
            const float* lg = lg0 + (size_t)j * HW;
            float m = 3.4e38f;
            #pragma unroll
            for (int k = 0; k < 8; k++) {
                int h = base + k;
                if (h < HW) m = fminf(m, Dkey_s(lg[h], cdv[k]));
            }
            mj[j] = m;
        }
    }
    #pragma unroll
    for (int j = 0; j < 8; j++) {
        float m = mj[j];
        #pragma unroll
        for (int o = 16; o; o >>= 1)
            m = fminf(m, __shfl_xor_sync(0xffffffffu, m, o));
        mj[j] = m;
    }
    if (lane == 0) {
        int sb = c_segb[l], spc = c_spc[l];
        #pragma unroll
        for (int j = 0; j < 8; j++)
            g_segD[n * NSEGPAD + sb + (grp * 8 + j) * spc + chunk] = mj[j];
    }
}

// segD buckets live in [2032, 4095] (D > 1) -> 256-entry offset histogram,
// single-warp ascending scan. Also zeroes g_cnt and g_hist2.
__global__ void __launch_bounds__(1024) k_cut() {
    __shared__ int hist[256];
    __shared__ int bres, lcnt_s;
    int n = blockIdx.x, tid = threadIdx.x;
    const int nt = 1024;
    int lane = tid & 31;
    if (tid < 256) hist[tid] = 0;
    for (int i = tid; i < 2048; i += nt) g_hist2[n][i] = 0;
    if (tid == 0) { bres = 255; lcnt_s = 0; g_cnt[n] = 0; }
    __syncthreads();
    for (int i = tid; i < NSEG; i += nt) {
        int b = (int)(__float_as_uint(g_segD[n * NSEGPAD + i]) >> 19) - BOFF;
        atomicAdd(&hist[min(max(b, 0), 255)], 1);
    }
    __syncthreads();
    if (tid < 32) {
        int cum = 0;
        for (int s0 = 0; s0 < 256; s0 += 32) {
            int v = hist[s0 + lane];
            int sc = v;
            #pragma unroll
            for (int o = 1; o < 32; o <<= 1) {
                int t2 = __shfl_up_sync(0xffffffffu, sc, o);
                if (lane >= o) sc += t2;
            }
            int tot = __shfl_sync(0xffffffffu, sc, 31);
            unsigned bal = __ballot_sync(0xffffffffu, cum + sc >= NREF);
            if (bal) { if (lane == 0) bres = s0 + __ffs(bal) - 1; break; }
            cum += tot;
        }
    }
    __syncthreads();
    int bc = BOFF + min(bres + 1, 255);  // absolute; +1 bucket surrogate slop
    if (tid == 0) g_bcut[n] = bc;
    for (int i = tid; i < NSEG; i += nt) {
        int b = (int)(__float_as_uint(g_segD[n * NSEGPAD + i]) >> 19);
        if (b <= bc) {
            int pos = atomicAdd(&lcnt_s, 1);
            if (pos < LCAP) g_seglist[n][pos] = i;
        }
    }
    __syncthreads();
    if (tid == 0) g_lcnt[n] = min(lcnt_s, LCAP);
}

// emit candidate AND bump the per-image exact-score histogram (stored-only,
// so k_sort's scan sees the identical multiset as the filter).
__device__ __forceinline__ void push_cand(int n, float a, float ctr_v, int rnk) {
    float sa = sig_ref(a);
    if (sa > 0.05f) {                           // exact reference gate
        float v = sa * sig_ref(ctr_v);
        if (v > 0.0f) {
            unsigned vb = __float_as_uint(v);
            unsigned long long kk =
                ((unsigned long long)vb << 32) |
                (0x7FFFFFFFu - (unsigned)rnk);
            int pos = atomicAdd(&g_cnt[n], 1);
            if (pos < CAP) {
                g_cand[n][pos] = kk;
                atomicAdd(&g_hist2[n][min(vb >> 19, 2047u)], 1);
            }
        }
    }
}

// flattened one-quad-per-thread, R11-proven grid (256,16).
__global__ void k_compact(P5 p) {
    int n = blockIdx.y;
    int bcut = g_bcut[n];
    int lcnt = g_lcnt[n];
    int total = lcnt << 6;              // 64 quads per 256-elem segment
    int stride = gridDim.x * blockDim.x;
    for (int e = blockIdx.x * blockDim.x + threadIdx.x; e < total; e += stride) {
        int si = g_seglist[n][e >> 6];
        Seg sg = seg_decode(si);
        int hw = sg.hw0 + ((e & 63) << 2);
        const float* lg = p.lg[sg.l] + ((size_t)n * NCLS + sg.c) * sg.HW;
        const float* ctp = p.ct[sg.l] + (size_t)n * sg.HW;
        int rb = c_rb[sg.l];
        if (sg.l < 2 && hw + 4 <= sg.HW) {
            float4 a = *(const float4*)(lg + hw);
            float4 t = *(const float4*)(ctp + hw);
            float aa[4] = {a.x, a.y, a.z, a.w};
            float tt[4] = {t.x, t.y, t.z, t.w};
            #pragma unroll
            for (int k = 0; k < 4; k++) {
                float cdv = __fadd_rn(1.0f, expneg_s(tt[k]));
                if ((int)(__float_as_uint(Dkey_s(aa[k], cdv)) >> 19) <= bcut)
                    push_cand(n, aa[k], tt[k], rb + (hw + k) * NCLS + sg.c);
            }
        } else {
            #pragma unroll
            for (int k = 0; k < 4; k++) {
                int h = hw + k;
                if (h < sg.HW) {
                    float a = lg[h];
                    float tv = ctp[h];
                    float cdv = __fadd_rn(1.0f, expneg_s(tv));
                    if ((int)(__float_as_uint(Dkey_s(a, cdv)) >> 19) <= bcut)
                        push_cand(n, a, tv, rb + h * NCLS + sg.c);
                }
            }
        }
    }
}

// top-256: hist scan -> filter (+64-way sub-hist of boundary bucket) ->
// refined 19-bit cut -> counting rank over ~270 -> ordered keys -> slot-
// parallel decode/scatter.
__global__ void __launch_bounds__(1024) k_sort(P5 p, float* out) {
    __shared__ u64 buf[1024];            // first-stage survivors (8KB)
    __shared__ u64 buf2[512];            // refined survivors (4KB)
    __shared__ u64 ord[NREF];            // ordered winning keys (2KB)
    __shared__ int subh[64];
    __shared__ int wtot[32], wsuf[32];
    __shared__ int m, m2, bs, scut, above_s;
    int n = blockIdx.x, tid = threadIdx.x;
    const int nt = 1024;
    int lane = tid & 31, w = tid >> 5;
    int cnt = min(g_cnt[n], CAP);
    if (tid < 64) subh[tid] = 0;
    if (tid < NREF) ord[tid] = 0;
    if (tid == 0) { m = 0; m2 = 0; bs = 0; scut = 0; above_s = 0; }
    __syncthreads();

    // descending rank-select over precomputed 2048 buckets (thread owns 2t,2t+1)
    {
        int c0 = g_hist2[n][2 * tid], c1 = g_hist2[n][2 * tid + 1];
        int s2 = c0 + c1;
        int suf = s2;
        #pragma unroll
        for (int o = 1; o < 32; o <<= 1) {
            int t2 = __shfl_down_sync(0xffffffffu, suf, o);
            if (lane + o < 32) suf += t2;
        }
        if (lane == 0) wtot[w] = suf;
        __syncthreads();
        if (tid < 32) {
            int v = wtot[tid];
            int s = v;
            #pragma unroll
            for (int o = 1; o < 32; o <<= 1) {
                int t2 = __shfl_down_sync(0xffffffffu, s, o);
                if (tid + o < 32) s += t2;
            }
            wsuf[tid] = s - v;
        }
        __syncthreads();
        int above = wsuf[w] + (suf - s2);
        if (above < NREF && above + s2 >= NREF) {
            int cum = above + c1;
            if (cum >= NREF)            { bs = 2 * tid + 1; above_s = above; }
            else if (cum + c0 >= NREF)  { bs = 2 * tid;     above_s = above + c1; }
        }
    }
    __syncthreads();
    int bcut2 = bs, abv = above_s;

    // filter: bucket > bs -> buf; bucket == bs -> buf + sub-histogram
    for (int i = tid; i < cnt; i += nt) {
        u64 kk = g_cand[n][i];
        int b = (int)(kk >> 51);
        if (b >= bcut2) {
            int pos = atomicAdd(&m, 1);
            if (pos < 1024) buf[pos] = kk;
            if (b == bcut2) atomicAdd(&subh[(int)(kk >> 45) & 63], 1);
        }
    }
    __syncthreads();
    int mm = min(m, 1024);

    // refine within boundary bucket: largest sub-cut with enough survivors
    if (tid < 32) {
        int need = NREF - abv;           // >= 1 by construction
        int cum = 0;
        for (int s0 = 32; s0 >= 0; s0 -= 32) {
            int v = subh[s0 + lane];
            int suf = v;
            #pragma unroll
            for (int o = 1; o < 32; o <<= 1) {
                int t2 = __shfl_down_sync(0xffffffffu, suf, o);
                if (lane + o < 32) suf += t2;
            }
            unsigned bal = __ballot_sync(0xffffffffu, cum + suf >= need);
            if (bal) {
                int hi = 31 - __clz(bal);
                if (lane == hi) scut = s0 + hi;
                break;
            }
            cum += __shfl_sync(0xffffffffu, suf, 0);
        }
    }
    __syncthreads();
    int cut19 = (bcut2 << 6) | scut;

    // refilter to refined survivor set (~NREF + eps)
    for (int i = tid; i < mm; i += nt) {
        u64 kk = buf[i];
        if ((int)(kk >> 45) >= cut19) {
            int pos = atomicAdd(&m2, 1);
            if (pos < 512) buf2[pos] = kk;
        }
    }
    __syncthreads();
    int mm2 = min(m2, 512);

    // counting rank (broadcast smem reads), winners -> ord[slot]
    for (int i = tid; i < mm2; i += nt) {
        u64 key = buf2[i];
        int slot = 0;
        for (int j = 0; j < mm2; j++)
            slot += (buf2[j] > key);
        if (slot < NREF) ord[slot] = key;
    }
    __syncthreads();

    // slot-parallel decode + write (slots with no winner stay zero)
    if (tid < NREF) {
        u64 key = ord[tid];
        float sc = 0.f, x0 = 0.f, y0 = 0.f, x1 = 0.f, y1 = 0.f;
        int cls = 0, lvl = 0;
        if (key) {
            float v = __uint_as_float((unsigned)(key >> 32));
            unsigned rank = 0x7FFFFFFFu - (unsigned)(key & 0xFFFFFFFFu);
            int l;
            if (rank < 1216000u) l = 0;
            else if (rank < 1520000u) l = 1;
            else if (rank < 1596000u) l = 2;
            else if (rank < 1615760u) l = 3;
            else l = 4;
            int HWl = c_HW[l];
            int r = (int)rank - c_rb[l];
            int loc = r / NCLS;
            cls = r - NCLS * loc;
            lvl = l;
            float strf = c_str[l];
            float px = p.lc[l][2 * loc], py = p.lc[l][2 * loc + 1];
            const float* rg = p.rg[l] + (size_t)n * 4 * HWl;
            float r0 = rg[loc] * strf;
            float r1 = rg[HWl + loc] * strf;
            float r2 = rg[2 * HWl + loc] * strf;
            float r3 = rg[3 * HWl + loc] * strf;
            sc = sqrtf(v);
            x0 = px - r0; y0 = py - r1; x1 = px + r2; y1 = py + r3;
        }
        int o = n * NREF + tid;
        out[o] = sc;
        float* ob = out + NIMG * NREF;
        ob[o * 4 + 0] = x0; ob[o * 4 + 1] = y0;
        ob[o * 4 + 2] = x1; ob[o * 4 + 3] = y1;
        out[NIMG * NREF * 5 + o] = (float)cls;
        out[NIMG * NREF * 6 + o] = (float)lvl;
    }
}

extern "C" void kernel_launch(void* const* d_in, const int* in_sizes, int n_in,
                              void* d_out, int out_size) {
    P5 p;
    for (int l = 0; l < 5; l++) {
        p.lg[l] = (const float*)d_in[4 * l + 0];
        p.rg[l] = (const float*)d_in[4 * l + 1];
        p.ct[l] = (const float*)d_in[4 * l + 2];
        p.lc[l] = (const float*)d_in[4 * l + 3];
    }
    dim3 g(102, NIMG);       // 102*8 = 816 warps >= 810 per image
    k_minred<<<g, 256>>>(p);
    k_cut<<<NIMG, 1024>>>();
    dim3 gc(256, NIMG);      // R11-proven compact config
    k_compact<<<gc, 256>>>(p);
    k_sort<<<NIMG, 1024>>>(p, (float*)d_out);
}